// round 3
// baseline (speedup 1.0000x reference)
#include <cuda_runtime.h>
#include <math.h>

#define NN 50000
#define DD 64
#define EE 800000
#define LAMB 0.8f

// ---------------- device workspace ----------------
__device__ __align__(16) float g_aggP[NN * DD];
__device__ __align__(16) float g_aggN[NN * DD];
__device__ __align__(16) float g_agg1[NN * DD];
__device__ __align__(16) float g_agg2[NN * DD];
__device__ __align__(16) float g_agg3[NN * DD];
__device__ __align__(16) float g_agg4[NN * DD];
__device__ __align__(16) float g_cntP[NN];
__device__ __align__(16) float g_cntN[NN];
__device__ __align__(16) float g_hpos[NN * DD];
__device__ __align__(16) float g_hneg[NN * DD];
__device__ __align__(16) float g_z[NN * 2 * DD];
__device__ __align__(16) float g_znorm[NN];
__device__ int   g_clar[NN];
__device__ int   g_comm[NN];
__device__ int   g_pe[2 * EE];      // normalized int32 pos edges (rows, then cols)
__device__ int   g_ne[2 * EE];      // normalized int32 neg edges
__device__ int   g_e64, g_c64;      // detected input widths
__device__ double g_acc[3];

// ---------------- helpers ----------------
__device__ __forceinline__ void red4(float* p, float4 v) {
    asm volatile("red.global.add.v4.f32 [%0], {%1,%2,%3,%4};"
                 :: "l"(p), "f"(v.x), "f"(v.y), "f"(v.z), "f"(v.w) : "memory");
}

__device__ __forceinline__ float warp_sum(float v) {
    #pragma unroll
    for (int o = 16; o > 0; o >>= 1) v += __shfl_xor_sync(0xffffffffu, v, o);
    return v;
}

__device__ __forceinline__ void block_accum(float v, double* acc) {
    __shared__ float red[8];
    float ws = warp_sum(v);
    int lane = threadIdx.x & 31, w = threadIdx.x >> 5;
    if (lane == 0) red[w] = ws;
    __syncthreads();
    if (w == 0) {
        float s = (lane < (blockDim.x >> 5)) ? red[lane] : 0.0f;
        s = warp_sum(s);
        if (lane == 0) atomicAdd(acc, (double)s);
    }
}

// ---------------- dtype detection + normalization ----------------
__global__ void detect_kernel(const void* pe, const void* cm) {
    if (threadIdx.x == 0 && blockIdx.x == 0) {
        const long long* p = (const long long*)pe;
        int ok = 1;
        for (int k = 0; k < 64; k++) {
            long long v = p[k];
            if (v < 0 || v >= NN) { ok = 0; break; }
        }
        g_e64 = ok;
        const long long* c = (const long long*)cm;
        int ok2 = 1;
        for (int k = 0; k < 64; k++) {
            long long v = c[k];
            if (v < 0 || v >= 3) { ok2 = 0; break; }
        }
        g_c64 = ok2;
    }
}

__global__ void convert_kernel(const void* pe, const void* ne, const void* cm) {
    int i = blockIdx.x * blockDim.x + threadIdx.x;
    int e64 = g_e64, c64 = g_c64;
    if (i < 2 * EE) {
        long long vp = e64 ? ((const long long*)pe)[i] : (long long)((const int*)pe)[i];
        long long vn = e64 ? ((const long long*)ne)[i] : (long long)((const int*)ne)[i];
        int ip = (int)vp, in = (int)vn;
        ip = ip < 0 ? 0 : (ip >= NN ? NN - 1 : ip);
        in = in < 0 ? 0 : (in >= NN ? NN - 1 : in);
        g_pe[i] = ip;
        g_ne[i] = in;
    }
    if (i < NN) {
        long long vc = c64 ? ((const long long*)cm)[i] : (long long)((const int*)cm)[i];
        int ic = (int)vc;
        g_comm[i] = ic < 0 ? 0 : (ic > 2 ? 2 : ic);
    }
}

// ---------------- kernels ----------------
__global__ void zero_kernel() {
    int i = blockIdx.x * blockDim.x + threadIdx.x;
    if (i < NN * DD) {
        g_aggP[i] = 0.f; g_aggN[i] = 0.f;
        g_agg1[i] = 0.f; g_agg2[i] = 0.f;
        g_agg3[i] = 0.f; g_agg4[i] = 0.f;
    }
    if (i < NN) { g_cntP[i] = 0.f; g_cntN[i] = 0.f; }
    if (i < 3) g_acc[i] = 0.0;
}

__global__ void scatter0_kernel(const int* __restrict__ er,
                                const int* __restrict__ ec,
                                const float* __restrict__ src,
                                float* __restrict__ agg,
                                float* __restrict__ cnt) {
    long long gid = (long long)blockIdx.x * blockDim.x + threadIdx.x;
    if (gid >= (long long)EE * 16) return;
    int e = (int)(gid >> 4), t = (int)(gid & 15);
    int row = er[e], col = ec[e];
    float4 v = ((const float4*)src)[col * 16 + t];
    red4(agg + row * DD + t * 4, v);
    if (t == 0) atomicAdd(cnt + row, 1.0f);
}

__global__ void scatter1_kernel(const int* __restrict__ er,
                                const int* __restrict__ ec,
                                const float* __restrict__ srcA, float* __restrict__ aggA,
                                const float* __restrict__ srcB, float* __restrict__ aggB) {
    long long gid = (long long)blockIdx.x * blockDim.x + threadIdx.x;
    if (gid >= (long long)EE * 16) return;
    int e = (int)(gid >> 4), t = (int)(gid & 15);
    int row = er[e], col = ec[e];
    float4 va = ((const float4*)srcA)[col * 16 + t];
    red4(aggA + row * DD + t * 4, va);
    float4 vb = ((const float4*)srcB)[col * 16 + t];
    red4(aggB + row * DD + t * 4, vb);
}

// dense + L2-normalize + tanh. One warp per node; each lane produces 2 outputs.
template <int K>
__global__ void dense_norm_tanh(const float* __restrict__ s0, const float* __restrict__ c0,
                                const float* __restrict__ s1, const float* __restrict__ c1,
                                const float* __restrict__ s2,
                                const float* __restrict__ W, const float* __restrict__ b,
                                float* __restrict__ out, int ostride, int ooff,
                                float* __restrict__ mirror) {
    extern __shared__ float Wsh[];  // K*64 floats
    for (int t = threadIdx.x; t < K * 64; t += blockDim.x) Wsh[t] = W[t];
    __syncthreads();

    int lane = threadIdx.x & 31;
    int node = blockIdx.x * (blockDim.x >> 5) + (threadIdx.x >> 5);
    if (node >= NN) return;

    float r[K / 32];
    float ic0 = c0 ? 1.0f / fmaxf(c0[node], 1.0f) : 1.0f;
    float ic1 = c1 ? 1.0f / fmaxf(c1[node], 1.0f) : 1.0f;
    #pragma unroll
    for (int q = 0; q < K / 32; q++) {
        int k = q * 32 + lane;
        int seg = k >> 6, w = k & 63;
        float v;
        if (seg == 0)      v = s0[node * 64 + w] * ic0;
        else if (seg == 1) v = s1[node * 64 + w] * ic1;
        else               v = s2[node * 64 + w];
        r[q] = v;
    }

    const float2* W2 = (const float2*)Wsh;
    float2 acc;
    acc.x = b[2 * lane];
    acc.y = b[2 * lane + 1];
    #pragma unroll
    for (int k = 0; k < K; k++) {
        float xk = __shfl_sync(0xffffffffu, r[k / 32], k % 32);
        float2 w2 = W2[k * 32 + lane];
        acc.x = fmaf(xk, w2.x, acc.x);
        acc.y = fmaf(xk, w2.y, acc.y);
    }

    float sumsq = warp_sum(acc.x * acc.x + acc.y * acc.y);
    float inv = 1.0f / fmaxf(sqrtf(sumsq), 1e-12f);
    float o0 = tanhf(acc.x * inv);
    float o1 = tanhf(acc.y * inv);
    float2 ov; ov.x = o0; ov.y = o1;
    *(float2*)(out + node * ostride + ooff + 2 * lane) = ov;
    if (mirror) {
        mirror[(size_t)node * 128 + ooff + 2 * lane]     = o0;
        mirror[(size_t)node * 128 + ooff + 2 * lane + 1] = o1;
    }
}

__global__ void reg_clarify_kernel(const float* __restrict__ Wr, const float* __restrict__ br,
                                   float* __restrict__ out_clar) {
    __shared__ float Ws[384];
    for (int t = threadIdx.x; t < 384; t += blockDim.x) Ws[t] = Wr[t];
    __syncthreads();

    int i = blockIdx.x * blockDim.x + threadIdx.x;
    float term = 0.0f;
    if (i < NN) {
        float l0 = br[0], l1 = br[1], l2 = br[2], sq = 0.0f;
        const float4* zr = (const float4*)(g_z + (size_t)i * 128);
        #pragma unroll
        for (int q = 0; q < 32; q++) {
            float4 v = zr[q];
            int k = q * 4;
            l0 += v.x * Ws[(k+0)*3+0] + v.y * Ws[(k+1)*3+0] + v.z * Ws[(k+2)*3+0] + v.w * Ws[(k+3)*3+0];
            l1 += v.x * Ws[(k+0)*3+1] + v.y * Ws[(k+1)*3+1] + v.z * Ws[(k+2)*3+1] + v.w * Ws[(k+3)*3+1];
            l2 += v.x * Ws[(k+0)*3+2] + v.y * Ws[(k+1)*3+2] + v.z * Ws[(k+2)*3+2] + v.w * Ws[(k+3)*3+2];
            sq += v.x*v.x + v.y*v.y + v.z*v.z + v.w*v.w;
        }
        g_znorm[i] = fmaxf(sqrtf(sq), 1e-8f);

        float m = fmaxf(l0, fmaxf(l1, l2));
        float lse = m + logf(expf(l0 - m) + expf(l1 - m) + expf(l2 - m));
        int cm = g_comm[i];
        float lc = (cm == 0) ? l0 : ((cm == 1) ? l1 : l2);
        term = lse - lc;

        int cls = 0; float best = l0;
        if (l1 > best) { best = l1; cls = 1; }
        if (l2 > best) { best = l2; cls = 2; }
        g_clar[i] = cls;
        if (out_clar) out_clar[i] = (float)cls;
    }
    block_accum(term, &g_acc[0]);
}

__global__ void sim_kernel(const int* __restrict__ er, const int* __restrict__ ec,
                           int mode) {
    long long gt = (long long)blockIdx.x * blockDim.x + threadIdx.x;
    int e = (int)(gt >> 5);
    int lane = threadIdx.x & 31;
    float contrib = 0.0f;
    if (e < EE) {
        int i = er[e], j = ec[e];
        const float4* zi = (const float4*)(g_z + (size_t)i * 128);
        const float4* zj = (const float4*)(g_z + (size_t)j * 128);
        float4 a = zi[lane], b = zj[lane];
        float d = a.x*b.x + a.y*b.y + a.z*b.z + a.w*b.w;
        d = warp_sum(d);
        if (lane == 0) {
            float cosv = d / (g_znorm[i] * g_znorm[j]);
            int ci = g_clar[i], cj = g_clar[j];
            if (mode == 0) contrib = (ci != cj) ? fmaxf(cosv, 0.0f) : 0.0f;
            else           contrib = (ci == cj) ? -fminf(cosv, 0.0f) : 0.0f;
        }
    }
    block_accum(contrib, &g_acc[1 + mode]);
}

__global__ void finalize_kernel(float* __restrict__ out) {
    double reg = g_acc[0] / (double)NN;
    double s1  = g_acc[1] / (double)EE;
    double s2  = g_acc[2] / (double)EE;
    out[0] = (float)(LAMB * reg + (1.0 - LAMB) * (s1 + s2));
}

// ---------------- launcher ----------------
extern "C" void kernel_launch(void* const* d_in, const int* in_sizes, int n_in,
                              void* d_out, int out_size) {
    const float *X = 0, *pbW = 0, *nbW = 0, *pdW = 0, *ndW = 0, *regW = 0, *regB = 0;
    const void *pe_raw = 0, *ne_raw = 0, *comm_raw = 0;
    const float* biases[4] = {0, 0, 0, 0};
    int nB = 0, nW2 = 0, nW3 = 0, nEdge = 0, nBig = 0;
    for (int i = 0; i < n_in; i++) {
        int sz = in_sizes[i];
        const void* p = d_in[i];
        if (sz == NN * DD)          { if (nBig == 0) X = (const float*)p; nBig++; }
        else if (sz == 2 * DD * DD) { if (nW2 == 0) pbW = (const float*)p; else nbW = (const float*)p; nW2++; }
        else if (sz == 3 * DD * DD) { if (nW3 == 0) pdW = (const float*)p; else ndW = (const float*)p; nW3++; }
        else if (sz == DD)          { if (nB < 4) biases[nB] = (const float*)p; nB++; }
        else if (sz == 2 * DD * 3)  { regW = (const float*)p; }
        else if (sz == 3)           { regB = (const float*)p; }
        else if (sz == 2 * EE)      { if (nEdge == 0) pe_raw = p; else ne_raw = p; nEdge++; }
        else if (sz == NN)          { comm_raw = p; }
    }
    const float* pbB = biases[0];
    const float* nbB = biases[1];
    const float* pdB = biases[2];
    const float* ndB = biases[3];

    float* out = (float*)d_out;
    float* z_mirror = (out_size >= 1 + NN * 128) ? out + 1 : nullptr;
    float* clar_out = (out_size >= 1 + NN * 128 + NN) ? out + 1 + (size_t)NN * 128 : nullptr;

    float* aggP; cudaGetSymbolAddress((void**)&aggP, g_aggP);
    float* aggN; cudaGetSymbolAddress((void**)&aggN, g_aggN);
    float* agg1; cudaGetSymbolAddress((void**)&agg1, g_agg1);
    float* agg2; cudaGetSymbolAddress((void**)&agg2, g_agg2);
    float* agg3; cudaGetSymbolAddress((void**)&agg3, g_agg3);
    float* agg4; cudaGetSymbolAddress((void**)&agg4, g_agg4);
    float* cntP; cudaGetSymbolAddress((void**)&cntP, g_cntP);
    float* cntN; cudaGetSymbolAddress((void**)&cntN, g_cntN);
    float* hpos; cudaGetSymbolAddress((void**)&hpos, g_hpos);
    float* hneg; cudaGetSymbolAddress((void**)&hneg, g_hneg);
    float* zbuf; cudaGetSymbolAddress((void**)&zbuf, g_z);
    int* peN; cudaGetSymbolAddress((void**)&peN, g_pe);
    int* neN; cudaGetSymbolAddress((void**)&neN, g_ne);

    const int TB = 256;

    detect_kernel<<<1, 32>>>(pe_raw, comm_raw);
    int cb = (2 * EE + TB - 1) / TB;
    convert_kernel<<<cb, TB>>>(pe_raw, ne_raw, comm_raw);

    int zb = (NN * DD + TB - 1) / TB;
    zero_kernel<<<zb, TB>>>();

    long long sthreads = (long long)EE * 16;
    int sblocks = (int)((sthreads + TB - 1) / TB);
    scatter0_kernel<<<sblocks, TB>>>(peN, peN + EE, X, aggP, cntP);
    scatter0_kernel<<<sblocks, TB>>>(neN, neN + EE, X, aggN, cntN);

    int dblocks = (NN + 7) / 8;
    dense_norm_tanh<128><<<dblocks, TB, 128 * 64 * 4>>>(
        aggP, cntP, X, nullptr, nullptr, pbW, pbB, hpos, 64, 0, nullptr);
    dense_norm_tanh<128><<<dblocks, TB, 128 * 64 * 4>>>(
        aggN, cntN, X, nullptr, nullptr, nbW, nbB, hneg, 64, 0, nullptr);

    scatter1_kernel<<<sblocks, TB>>>(peN, peN + EE, hpos, agg1, hneg, agg3);
    scatter1_kernel<<<sblocks, TB>>>(neN, neN + EE, hneg, agg2, hpos, agg4);

    dense_norm_tanh<192><<<dblocks, TB, 192 * 64 * 4>>>(
        agg1, cntP, agg2, cntN, hpos, pdW, pdB, zbuf, 128, 0, z_mirror);
    dense_norm_tanh<192><<<dblocks, TB, 192 * 64 * 4>>>(
        agg3, cntP, agg4, cntN, hneg, ndW, ndB, zbuf, 128, 64, z_mirror);

    int rblocks = (NN + TB - 1) / TB;
    reg_clarify_kernel<<<rblocks, TB>>>(regW, regB, clar_out);

    long long simthreads = (long long)EE * 32;
    int simblocks = (int)((simthreads + TB - 1) / TB);
    sim_kernel<<<simblocks, TB>>>(peN, peN + EE, 0);
    sim_kernel<<<simblocks, TB>>>(neN, neN + EE, 1);

    if (out_size >= 1) finalize_kernel<<<1, 1>>>(out);
}

// round 4
// speedup vs baseline: 1.0743x; 1.0743x over previous
#include <cuda_runtime.h>
#include <math.h>

#define NN 50000
#define DD 64
#define EE 800000
#define LAMB 0.8f

// ---------------- device workspace ----------------
__device__ __align__(16) float g_aggP[NN * DD];
__device__ __align__(16) float g_aggN[NN * DD];
__device__ __align__(16) float g_agg1[NN * DD];   // posmean(h_pos)
__device__ __align__(16) float g_agg2[NN * DD];   // negmean(h_neg)
__device__ __align__(16) float g_agg3[NN * DD];   // posmean(h_neg)
__device__ __align__(16) float g_agg4[NN * DD];   // negmean(h_pos)
__device__ __align__(16) float g_hpos[NN * DD];
__device__ __align__(16) float g_hneg[NN * DD];
__device__ __align__(16) float g_z[NN * 2 * DD];
__device__ __align__(16) float g_znorm[NN];
__device__ int   g_icntP[NN];
__device__ int   g_icntN[NN];
__device__ int   g_clar[NN];
__device__ int   g_comm[NN];
__device__ __align__(8) int2 g_peRC[EE];   // (row, col) int32
__device__ __align__(8) int2 g_neRC[EE];
__device__ int   g_e64, g_c64;
__device__ double g_accs[3 * 64];          // spread accumulator slots

// ---------------- helpers ----------------
__device__ __forceinline__ void red4(float* p, float4 v) {
    asm volatile("red.global.add.v4.f32 [%0], {%1,%2,%3,%4};"
                 :: "l"(p), "f"(v.x), "f"(v.y), "f"(v.z), "f"(v.w) : "memory");
}

__device__ __forceinline__ float warp_sum(float v) {
    #pragma unroll
    for (int o = 16; o > 0; o >>= 1) v += __shfl_xor_sync(0xffffffffu, v, o);
    return v;
}

// block reduce then atomicAdd into a hashed slot of category cat
__device__ __forceinline__ void block_accum(float v, int cat) {
    __shared__ float red[8];
    float ws = warp_sum(v);
    int lane = threadIdx.x & 31, w = threadIdx.x >> 5;
    if (lane == 0) red[w] = ws;
    __syncthreads();
    if (w == 0) {
        float s = (lane < (blockDim.x >> 5)) ? red[lane] : 0.0f;
        s = warp_sum(s);
        if (lane == 0) atomicAdd(&g_accs[cat * 64 + (blockIdx.x & 63)], (double)s);
    }
}

// ---------------- dtype detection + normalization ----------------
__global__ void detect_kernel(const void* pe, const void* cm) {
    if (threadIdx.x == 0 && blockIdx.x == 0) {
        const long long* p = (const long long*)pe;
        int ok = 1;
        for (int k = 0; k < 64; k++) {
            long long v = p[k];
            if (v < 0 || v >= NN) { ok = 0; break; }
        }
        g_e64 = ok;
        const long long* c = (const long long*)cm;
        int ok2 = 1;
        for (int k = 0; k < 64; k++) {
            long long v = c[k];
            if (v < 0 || v >= 3) { ok2 = 0; break; }
        }
        g_c64 = ok2;
    }
}

__global__ void zero_kernel() {
    int i = blockIdx.x * blockDim.x + threadIdx.x;
    float4 z4 = make_float4(0.f, 0.f, 0.f, 0.f);
    if (i < NN * DD / 4) {
        ((float4*)g_aggP)[i] = z4; ((float4*)g_aggN)[i] = z4;
        ((float4*)g_agg1)[i] = z4; ((float4*)g_agg2)[i] = z4;
        ((float4*)g_agg3)[i] = z4; ((float4*)g_agg4)[i] = z4;
    }
    if (i < NN) { g_icntP[i] = 0; g_icntN[i] = 0; }
    if (i < 3 * 64) g_accs[i] = 0.0;
}

__device__ __forceinline__ int ld_idx(const void* p, int i, int is64, int lim) {
    long long v = is64 ? ((const long long*)p)[i] : (long long)((const int*)p)[i];
    int x = (int)v;
    return x < 0 ? 0 : (x >= lim ? lim - 1 : x);
}

// convert edges to int2 (row,col), accumulate degree counts, convert comm
__global__ void convert_kernel(const void* pe, const void* ne, const void* cm) {
    int i = blockIdx.x * blockDim.x + threadIdx.x;
    int e64 = g_e64, c64 = g_c64;
    if (i < EE) {
        int rp = ld_idx(pe, i, e64, NN);
        int cp = ld_idx(pe, EE + i, e64, NN);
        int rn = ld_idx(ne, i, e64, NN);
        int cn = ld_idx(ne, EE + i, e64, NN);
        g_peRC[i] = make_int2(rp, cp);
        g_neRC[i] = make_int2(rn, cn);
        atomicAdd(&g_icntP[rp], 1);
        atomicAdd(&g_icntN[rn], 1);
    }
    if (i < NN) {
        int ic = ld_idx(cm, i, c64, 3);
        g_comm[i] = ic;
    }
}

// ---------------- scatter kernels (paired P+N for MLP) ----------------
// layer0: aggP[rowP] += X[colP]; aggN[rowN] += X[colN]
__global__ void scatter0_both(const float* __restrict__ X) {
    long long gid = (long long)blockIdx.x * blockDim.x + threadIdx.x;
    if (gid >= (long long)EE * 16) return;
    int e = (int)(gid >> 4), t = (int)(gid & 15);
    int2 ep = g_peRC[e];
    int2 en = g_neRC[e];
    float4 vp = ((const float4*)X)[ep.y * 16 + t];
    float4 vn = ((const float4*)X)[en.y * 16 + t];
    red4(g_aggP + ep.x * DD + t * 4, vp);
    red4(g_aggN + en.x * DD + t * 4, vn);
}

// layer1: P: agg1+=hpos[colP], agg3+=hneg[colP];  N: agg2+=hneg[colN], agg4+=hpos[colN]
__global__ void scatter1_both() {
    long long gid = (long long)blockIdx.x * blockDim.x + threadIdx.x;
    if (gid >= (long long)EE * 16) return;
    int e = (int)(gid >> 4), t = (int)(gid & 15);
    int2 ep = g_peRC[e];
    int2 en = g_neRC[e];
    float4 v1 = ((const float4*)g_hpos)[ep.y * 16 + t];
    float4 v3 = ((const float4*)g_hneg)[ep.y * 16 + t];
    float4 v2 = ((const float4*)g_hneg)[en.y * 16 + t];
    float4 v4 = ((const float4*)g_hpos)[en.y * 16 + t];
    red4(g_agg1 + ep.x * DD + t * 4, v1);
    red4(g_agg3 + ep.x * DD + t * 4, v3);
    red4(g_agg2 + en.x * DD + t * 4, v2);
    red4(g_agg4 + en.x * DD + t * 4, v4);
}

// ---------------- dense + L2norm + tanh (persistent blocks) ----------------
template <int K>
__global__ void dense_norm_tanh(const float* __restrict__ s0, const int* __restrict__ c0,
                                const float* __restrict__ s1, const int* __restrict__ c1,
                                const float* __restrict__ s2,
                                const float* __restrict__ W, const float* __restrict__ b,
                                float* __restrict__ out, int ostride, int ooff,
                                float* __restrict__ mirror) {
    extern __shared__ float Wsh[];  // K*64 floats
    for (int t = threadIdx.x; t < K * 64; t += blockDim.x) Wsh[t] = W[t];
    __syncthreads();

    int lane = threadIdx.x & 31;
    int wid = threadIdx.x >> 5;
    int wpb = blockDim.x >> 5;
    float2 bias = ((const float2*)b)[lane];
    const float2* W2 = (const float2*)Wsh;

    for (int node = blockIdx.x * wpb + wid; node < NN; node += gridDim.x * wpb) {
        float ic0 = c0 ? 1.0f / (float)max(c0[node], 1) : 1.0f;
        float ic1 = c1 ? 1.0f / (float)max(c1[node], 1) : 1.0f;
        float r[K / 32];
        #pragma unroll
        for (int q = 0; q < K / 32; q++) {
            int k = q * 32 + lane;
            int seg = k >> 6, w = k & 63;
            float v;
            if (seg == 0)      v = s0[node * 64 + w] * ic0;
            else if (seg == 1) v = s1[node * 64 + w] * ic1;
            else               v = s2[node * 64 + w];
            r[q] = v;
        }

        float2 acc = bias;
        #pragma unroll
        for (int k = 0; k < K; k++) {
            float xk = __shfl_sync(0xffffffffu, r[k / 32], k % 32);
            float2 w2 = W2[k * 32 + lane];
            acc.x = fmaf(xk, w2.x, acc.x);
            acc.y = fmaf(xk, w2.y, acc.y);
        }

        float sumsq = warp_sum(acc.x * acc.x + acc.y * acc.y);
        float inv = 1.0f / fmaxf(sqrtf(sumsq), 1e-12f);
        float o0 = tanhf(acc.x * inv);
        float o1 = tanhf(acc.y * inv);
        float2 ov; ov.x = o0; ov.y = o1;
        *(float2*)(out + (size_t)node * ostride + ooff + 2 * lane) = ov;
        if (mirror) {
            mirror[(size_t)node * 128 + ooff + 2 * lane]     = o0;
            mirror[(size_t)node * 128 + ooff + 2 * lane + 1] = o1;
        }
    }
}

// ---------------- logits / argmax / nll / znorm ----------------
__global__ void reg_clarify_kernel(const float* __restrict__ Wr, const float* __restrict__ br,
                                   float* __restrict__ out_clar) {
    __shared__ float Ws[384];
    for (int t = threadIdx.x; t < 384; t += blockDim.x) Ws[t] = Wr[t];
    __syncthreads();

    int i = blockIdx.x * blockDim.x + threadIdx.x;
    float term = 0.0f;
    if (i < NN) {
        float l0 = br[0], l1 = br[1], l2 = br[2], sq = 0.0f;
        const float4* zr = (const float4*)(g_z + (size_t)i * 128);
        #pragma unroll
        for (int q = 0; q < 32; q++) {
            float4 v = zr[q];
            int k = q * 4;
            l0 += v.x * Ws[(k+0)*3+0] + v.y * Ws[(k+1)*3+0] + v.z * Ws[(k+2)*3+0] + v.w * Ws[(k+3)*3+0];
            l1 += v.x * Ws[(k+0)*3+1] + v.y * Ws[(k+1)*3+1] + v.z * Ws[(k+2)*3+1] + v.w * Ws[(k+3)*3+1];
            l2 += v.x * Ws[(k+0)*3+2] + v.y * Ws[(k+1)*3+2] + v.z * Ws[(k+2)*3+2] + v.w * Ws[(k+3)*3+2];
            sq += v.x*v.x + v.y*v.y + v.z*v.z + v.w*v.w;
        }
        g_znorm[i] = fmaxf(sqrtf(sq), 1e-8f);

        float m = fmaxf(l0, fmaxf(l1, l2));
        float lse = m + logf(expf(l0 - m) + expf(l1 - m) + expf(l2 - m));
        int cm = g_comm[i];
        float lc = (cm == 0) ? l0 : ((cm == 1) ? l1 : l2);
        term = lse - lc;

        int cls = 0; float best = l0;
        if (l1 > best) { best = l1; cls = 1; }
        if (l2 > best) { best = l2; cls = 2; }
        g_clar[i] = cls;
        if (out_clar) out_clar[i] = (float)cls;
    }
    block_accum(term, 0);
}

// ---------------- cosine sim losses (mode-pure blocks) ----------------
#define POS_BLOCKS (EE / 8)   // 8 warps per block, one edge per warp
__global__ void sim_both() {
    int neg = (blockIdx.x >= POS_BLOCKS) ? 1 : 0;
    int bid = neg ? blockIdx.x - POS_BLOCKS : blockIdx.x;
    int e = bid * 8 + (threadIdx.x >> 5);
    int lane = threadIdx.x & 31;
    float contrib = 0.0f;
    {
        int2 ed = neg ? g_neRC[e] : g_peRC[e];
        int i = ed.x, j = ed.y;
        const float4* zi = (const float4*)(g_z + (size_t)i * 128);
        const float4* zj = (const float4*)(g_z + (size_t)j * 128);
        float4 a = zi[lane], b = zj[lane];
        float d = a.x*b.x + a.y*b.y + a.z*b.z + a.w*b.w;
        d = warp_sum(d);
        if (lane == 0) {
            float cosv = d / (g_znorm[i] * g_znorm[j]);
            int ci = g_clar[i], cj = g_clar[j];
            if (!neg) contrib = (ci != cj) ? fmaxf(cosv, 0.0f) : 0.0f;
            else      contrib = (ci == cj) ? -fminf(cosv, 0.0f) : 0.0f;
        }
    }
    block_accum(contrib, 1 + neg);
}

__global__ void finalize_kernel(float* __restrict__ out) {
    double reg = 0.0, s1 = 0.0, s2 = 0.0;
    for (int k = 0; k < 64; k++) {
        reg += g_accs[k];
        s1  += g_accs[64 + k];
        s2  += g_accs[128 + k];
    }
    reg /= (double)NN; s1 /= (double)EE; s2 /= (double)EE;
    out[0] = (float)(LAMB * reg + (1.0 - LAMB) * (s1 + s2));
}

// ---------------- launcher ----------------
extern "C" void kernel_launch(void* const* d_in, const int* in_sizes, int n_in,
                              void* d_out, int out_size) {
    const float *X = 0, *pbW = 0, *nbW = 0, *pdW = 0, *ndW = 0, *regW = 0, *regB = 0;
    const void *pe_raw = 0, *ne_raw = 0, *comm_raw = 0;
    const float* biases[4] = {0, 0, 0, 0};
    int nB = 0, nW2 = 0, nW3 = 0, nEdge = 0, nBig = 0;
    for (int i = 0; i < n_in; i++) {
        int sz = in_sizes[i];
        const void* p = d_in[i];
        if (sz == NN * DD)          { if (nBig == 0) X = (const float*)p; nBig++; }
        else if (sz == 2 * DD * DD) { if (nW2 == 0) pbW = (const float*)p; else nbW = (const float*)p; nW2++; }
        else if (sz == 3 * DD * DD) { if (nW3 == 0) pdW = (const float*)p; else ndW = (const float*)p; nW3++; }
        else if (sz == DD)          { if (nB < 4) biases[nB] = (const float*)p; nB++; }
        else if (sz == 2 * DD * 3)  { regW = (const float*)p; }
        else if (sz == 3)           { regB = (const float*)p; }
        else if (sz == 2 * EE)      { if (nEdge == 0) pe_raw = p; else ne_raw = p; nEdge++; }
        else if (sz == NN)          { comm_raw = p; }
    }
    const float* pbB = biases[0];
    const float* nbB = biases[1];
    const float* pdB = biases[2];
    const float* ndB = biases[3];

    float* out = (float*)d_out;
    float* z_mirror = (out_size >= 1 + NN * 128) ? out + 1 : nullptr;
    float* clar_out = (out_size >= 1 + NN * 128 + NN) ? out + 1 + (size_t)NN * 128 : nullptr;

    float* aggP; cudaGetSymbolAddress((void**)&aggP, g_aggP);
    float* aggN; cudaGetSymbolAddress((void**)&aggN, g_aggN);
    float* agg1; cudaGetSymbolAddress((void**)&agg1, g_agg1);
    float* agg2; cudaGetSymbolAddress((void**)&agg2, g_agg2);
    float* agg3; cudaGetSymbolAddress((void**)&agg3, g_agg3);
    float* agg4; cudaGetSymbolAddress((void**)&agg4, g_agg4);
    int* cntP; cudaGetSymbolAddress((void**)&cntP, g_icntP);
    int* cntN; cudaGetSymbolAddress((void**)&cntN, g_icntN);
    float* hpos; cudaGetSymbolAddress((void**)&hpos, g_hpos);
    float* hneg; cudaGetSymbolAddress((void**)&hneg, g_hneg);
    float* zbuf; cudaGetSymbolAddress((void**)&zbuf, g_z);

    const int TB = 256;

    detect_kernel<<<1, 32>>>(pe_raw, comm_raw);
    zero_kernel<<<(NN * DD / 4 + TB - 1) / TB, TB>>>();
    convert_kernel<<<(EE + TB - 1) / TB, TB>>>(pe_raw, ne_raw, comm_raw);

    long long sthreads = (long long)EE * 16;
    int sblocks = (int)((sthreads + TB - 1) / TB);
    scatter0_both<<<sblocks, TB>>>(X);

    const int DG = 592;   // 4 persistent blocks per SM
    dense_norm_tanh<128><<<DG, TB, 128 * 64 * 4>>>(
        aggP, cntP, X, nullptr, nullptr, pbW, pbB, hpos, 64, 0, nullptr);
    dense_norm_tanh<128><<<DG, TB, 128 * 64 * 4>>>(
        aggN, cntN, X, nullptr, nullptr, nbW, nbB, hneg, 64, 0, nullptr);

    scatter1_both<<<sblocks, TB>>>();

    dense_norm_tanh<192><<<DG, TB, 192 * 64 * 4>>>(
        agg1, cntP, agg2, cntN, hpos, pdW, pdB, zbuf, 128, 0, z_mirror);
    dense_norm_tanh<192><<<DG, TB, 192 * 64 * 4>>>(
        agg3, cntP, agg4, cntN, hneg, ndW, ndB, zbuf, 128, 64, z_mirror);

    reg_clarify_kernel<<<(NN + TB - 1) / TB, TB>>>(regW, regB, clar_out);

    sim_both<<<2 * POS_BLOCKS, TB>>>();

    if (out_size >= 1) finalize_kernel<<<1, 1>>>(out);
}

// round 5
// speedup vs baseline: 1.2067x; 1.1232x over previous
#include <cuda_runtime.h>
#include <cuda_bf16.h>
#include <math.h>

#define NN 50000
#define DD 64
#define EE 800000
#define LAMB 0.8f

// ---------------- device workspace ----------------
__device__ __align__(16) float g_aggP[NN * DD];
__device__ __align__(16) float g_aggN[NN * DD];
__device__ __align__(16) float g_agg1[NN * DD];   // posmean(h_pos)
__device__ __align__(16) float g_agg2[NN * DD];   // negmean(h_neg)
__device__ __align__(16) float g_agg3[NN * DD];   // posmean(h_neg)
__device__ __align__(16) float g_agg4[NN * DD];   // negmean(h_pos)
__device__ __align__(16) float g_hpos[NN * DD];
__device__ __align__(16) float g_hneg[NN * DD];
__device__ __align__(16) float g_z[NN * 2 * DD];
__device__ __align__(16) __nv_bfloat16 g_zh[NN * 2 * DD];  // bf16 shadow of z for sim
__device__ __align__(16) float g_znorm[NN];
__device__ int   g_icntP[NN];
__device__ int   g_icntN[NN];
__device__ int   g_clar[NN];
__device__ int   g_comm[NN];
__device__ __align__(8) int2 g_peRC[EE];   // (row, col) int32
__device__ __align__(8) int2 g_neRC[EE];
__device__ int   g_e64, g_c64;
__device__ double g_accs[3 * 64];          // spread accumulator slots

// ---------------- helpers ----------------
__device__ __forceinline__ void red4(float* p, float4 v) {
    asm volatile("red.global.add.v4.f32 [%0], {%1,%2,%3,%4};"
                 :: "l"(p), "f"(v.x), "f"(v.y), "f"(v.z), "f"(v.w) : "memory");
}

__device__ __forceinline__ float warp_sum(float v) {
    #pragma unroll
    for (int o = 16; o > 0; o >>= 1) v += __shfl_xor_sync(0xffffffffu, v, o);
    return v;
}

__device__ __forceinline__ void block_accum(float v, int cat) {
    __shared__ float red[8];
    float ws = warp_sum(v);
    int lane = threadIdx.x & 31, w = threadIdx.x >> 5;
    if (lane == 0) red[w] = ws;
    __syncthreads();
    if (w == 0) {
        float s = (lane < (blockDim.x >> 5)) ? red[lane] : 0.0f;
        s = warp_sum(s);
        if (lane == 0) atomicAdd(&g_accs[cat * 64 + (blockIdx.x & 63)], (double)s);
    }
}

// ---------------- dtype detection + normalization ----------------
__global__ void detect_kernel(const void* pe, const void* cm) {
    if (threadIdx.x == 0 && blockIdx.x == 0) {
        const long long* p = (const long long*)pe;
        int ok = 1;
        for (int k = 0; k < 64; k++) {
            long long v = p[k];
            if (v < 0 || v >= NN) { ok = 0; break; }
        }
        g_e64 = ok;
        const long long* c = (const long long*)cm;
        int ok2 = 1;
        for (int k = 0; k < 64; k++) {
            long long v = c[k];
            if (v < 0 || v >= 3) { ok2 = 0; break; }
        }
        g_c64 = ok2;
    }
}

__global__ void zero_kernel() {
    int i = blockIdx.x * blockDim.x + threadIdx.x;
    float4 z4 = make_float4(0.f, 0.f, 0.f, 0.f);
    if (i < NN * DD / 4) {
        ((float4*)g_aggP)[i] = z4; ((float4*)g_aggN)[i] = z4;
        ((float4*)g_agg1)[i] = z4; ((float4*)g_agg2)[i] = z4;
        ((float4*)g_agg3)[i] = z4; ((float4*)g_agg4)[i] = z4;
    }
    if (i < NN) { g_icntP[i] = 0; g_icntN[i] = 0; }
    if (i < 3 * 64) g_accs[i] = 0.0;
}

__device__ __forceinline__ int ld_idx(const void* p, int i, int is64, int lim) {
    long long v = is64 ? ((const long long*)p)[i] : (long long)((const int*)p)[i];
    int x = (int)v;
    return x < 0 ? 0 : (x >= lim ? lim - 1 : x);
}

__global__ void convert_kernel(const void* pe, const void* ne, const void* cm) {
    int i = blockIdx.x * blockDim.x + threadIdx.x;
    int e64 = g_e64, c64 = g_c64;
    if (i < EE) {
        int rp = ld_idx(pe, i, e64, NN);
        int cp = ld_idx(pe, EE + i, e64, NN);
        int rn = ld_idx(ne, i, e64, NN);
        int cn = ld_idx(ne, EE + i, e64, NN);
        g_peRC[i] = make_int2(rp, cp);
        g_neRC[i] = make_int2(rn, cn);
        atomicAdd(&g_icntP[rp], 1);
        atomicAdd(&g_icntN[rn], 1);
    }
    if (i < NN) {
        int ic = ld_idx(cm, i, c64, 3);
        g_comm[i] = ic;
    }
}

// ---------------- scatter kernels (2 edges/thread, paired P+N) ----------------
__global__ void scatter0_both(const float* __restrict__ X) {
    long long gid = (long long)blockIdx.x * blockDim.x + threadIdx.x;
    if (gid >= (long long)(EE / 2) * 16) return;
    int e = (int)(gid >> 4), t = (int)(gid & 15);
    int e2 = e + EE / 2;
    int2 p1 = g_peRC[e],  n1 = g_neRC[e];
    int2 p2 = g_peRC[e2], n2 = g_neRC[e2];
    const float4* X4 = (const float4*)X;
    float4 a = X4[p1.y * 16 + t];
    float4 b = X4[n1.y * 16 + t];
    float4 c = X4[p2.y * 16 + t];
    float4 d = X4[n2.y * 16 + t];
    red4(g_aggP + p1.x * DD + t * 4, a);
    red4(g_aggN + n1.x * DD + t * 4, b);
    red4(g_aggP + p2.x * DD + t * 4, c);
    red4(g_aggN + n2.x * DD + t * 4, d);
}

__global__ void scatter1_both() {
    long long gid = (long long)blockIdx.x * blockDim.x + threadIdx.x;
    if (gid >= (long long)(EE / 2) * 16) return;
    int e = (int)(gid >> 4), t = (int)(gid & 15);
    int e2 = e + EE / 2;
    int2 p1 = g_peRC[e],  n1 = g_neRC[e];
    int2 p2 = g_peRC[e2], n2 = g_neRC[e2];
    const float4* HP = (const float4*)g_hpos;
    const float4* HN = (const float4*)g_hneg;
    float4 v1a = HP[p1.y * 16 + t];
    float4 v3a = HN[p1.y * 16 + t];
    float4 v2a = HN[n1.y * 16 + t];
    float4 v4a = HP[n1.y * 16 + t];
    float4 v1b = HP[p2.y * 16 + t];
    float4 v3b = HN[p2.y * 16 + t];
    float4 v2b = HN[n2.y * 16 + t];
    float4 v4b = HP[n2.y * 16 + t];
    red4(g_agg1 + p1.x * DD + t * 4, v1a);
    red4(g_agg3 + p1.x * DD + t * 4, v3a);
    red4(g_agg2 + n1.x * DD + t * 4, v2a);
    red4(g_agg4 + n1.x * DD + t * 4, v4a);
    red4(g_agg1 + p2.x * DD + t * 4, v1b);
    red4(g_agg3 + p2.x * DD + t * 4, v3b);
    red4(g_agg2 + n2.x * DD + t * 4, v2b);
    red4(g_agg4 + n2.x * DD + t * 4, v4b);
}

// ---------------- dense + L2norm + tanh (persistent blocks) ----------------
template <int K>
__global__ void dense_norm_tanh(const float* __restrict__ s0, const int* __restrict__ c0,
                                const float* __restrict__ s1, const int* __restrict__ c1,
                                const float* __restrict__ s2,
                                const float* __restrict__ W, const float* __restrict__ b,
                                float* __restrict__ out, int ostride, int ooff,
                                float* __restrict__ mirror, __nv_bfloat16* __restrict__ zh) {
    extern __shared__ float Wsh[];  // K*64 floats
    for (int t = threadIdx.x; t < K * 64; t += blockDim.x) Wsh[t] = W[t];
    __syncthreads();

    int lane = threadIdx.x & 31;
    int wid = threadIdx.x >> 5;
    int wpb = blockDim.x >> 5;
    float2 bias = ((const float2*)b)[lane];
    const float2* W2 = (const float2*)Wsh;

    for (int node = blockIdx.x * wpb + wid; node < NN; node += gridDim.x * wpb) {
        float ic0 = c0 ? 1.0f / (float)max(c0[node], 1) : 1.0f;
        float ic1 = c1 ? 1.0f / (float)max(c1[node], 1) : 1.0f;
        float r[K / 32];
        #pragma unroll
        for (int q = 0; q < K / 32; q++) {
            int k = q * 32 + lane;
            int seg = k >> 6, w = k & 63;
            float v;
            if (seg == 0)      v = s0[node * 64 + w] * ic0;
            else if (seg == 1) v = s1[node * 64 + w] * ic1;
            else               v = s2[node * 64 + w];
            r[q] = v;
        }

        float2 acc = bias;
        #pragma unroll
        for (int k = 0; k < K; k++) {
            float xk = __shfl_sync(0xffffffffu, r[k / 32], k % 32);
            float2 w2 = W2[k * 32 + lane];
            acc.x = fmaf(xk, w2.x, acc.x);
            acc.y = fmaf(xk, w2.y, acc.y);
        }

        float sumsq = warp_sum(acc.x * acc.x + acc.y * acc.y);
        float inv = 1.0f / fmaxf(sqrtf(sumsq), 1e-12f);
        float o0 = tanhf(acc.x * inv);
        float o1 = tanhf(acc.y * inv);
        float2 ov; ov.x = o0; ov.y = o1;
        *(float2*)(out + (size_t)node * ostride + ooff + 2 * lane) = ov;
        if (mirror) {
            mirror[(size_t)node * 128 + ooff + 2 * lane]     = o0;
            mirror[(size_t)node * 128 + ooff + 2 * lane + 1] = o1;
        }
        if (zh) {
            *(__nv_bfloat162*)(zh + (size_t)node * 128 + ooff + 2 * lane) =
                __float22bfloat162_rn(ov);
        }
    }
}

// ---------------- logits / argmax / nll / znorm (f32 path — exact) ----------------
__global__ void reg_clarify_kernel(const float* __restrict__ Wr, const float* __restrict__ br,
                                   float* __restrict__ out_clar) {
    __shared__ float Ws[384];
    for (int t = threadIdx.x; t < 384; t += blockDim.x) Ws[t] = Wr[t];
    __syncthreads();

    int i = blockIdx.x * blockDim.x + threadIdx.x;
    float term = 0.0f;
    if (i < NN) {
        float l0 = br[0], l1 = br[1], l2 = br[2], sq = 0.0f;
        const float4* zr = (const float4*)(g_z + (size_t)i * 128);
        #pragma unroll
        for (int q = 0; q < 32; q++) {
            float4 v = zr[q];
            int k = q * 4;
            l0 += v.x * Ws[(k+0)*3+0] + v.y * Ws[(k+1)*3+0] + v.z * Ws[(k+2)*3+0] + v.w * Ws[(k+3)*3+0];
            l1 += v.x * Ws[(k+0)*3+1] + v.y * Ws[(k+1)*3+1] + v.z * Ws[(k+2)*3+1] + v.w * Ws[(k+3)*3+1];
            l2 += v.x * Ws[(k+0)*3+2] + v.y * Ws[(k+1)*3+2] + v.z * Ws[(k+2)*3+2] + v.w * Ws[(k+3)*3+2];
            sq += v.x*v.x + v.y*v.y + v.z*v.z + v.w*v.w;
        }
        g_znorm[i] = fmaxf(sqrtf(sq), 1e-8f);

        float m = fmaxf(l0, fmaxf(l1, l2));
        float lse = m + logf(expf(l0 - m) + expf(l1 - m) + expf(l2 - m));
        int cm = g_comm[i];
        float lc = (cm == 0) ? l0 : ((cm == 1) ? l1 : l2);
        term = lse - lc;

        int cls = 0; float best = l0;
        if (l1 > best) { best = l1; cls = 1; }
        if (l2 > best) { best = l2; cls = 2; }
        g_clar[i] = cls;
        if (out_clar) out_clar[i] = (float)cls;
    }
    block_accum(term, 0);
}

// ---------------- cosine sim losses: bf16 rows, 4 edges per warp ----------------
#define SIM_EPW 4
#define SIM_BLOCKS (EE / (SIM_EPW * 8))   // 8 warps/block
__global__ void sim_both() {
    int neg = (blockIdx.x >= SIM_BLOCKS) ? 1 : 0;
    int bid = neg ? blockIdx.x - SIM_BLOCKS : blockIdx.x;
    int warp = bid * 8 + (threadIdx.x >> 5);
    int lane = threadIdx.x & 31;
    int base = warp * SIM_EPW;
    const int2* RC = neg ? g_neRC : g_peRC;

    int2 ed[SIM_EPW];
    #pragma unroll
    for (int u = 0; u < SIM_EPW; u++) ed[u] = RC[base + u];

    uint2 va[SIM_EPW], vb[SIM_EPW];
    #pragma unroll
    for (int u = 0; u < SIM_EPW; u++) {
        va[u] = ((const uint2*)(g_zh + (size_t)ed[u].x * 128))[lane];
        vb[u] = ((const uint2*)(g_zh + (size_t)ed[u].y * 128))[lane];
    }

    float contrib = 0.0f;
    #pragma unroll
    for (int u = 0; u < SIM_EPW; u++) {
        float2 a0 = __bfloat1622float2(*(const __nv_bfloat162*)&va[u].x);
        float2 a1 = __bfloat1622float2(*(const __nv_bfloat162*)&va[u].y);
        float2 b0 = __bfloat1622float2(*(const __nv_bfloat162*)&vb[u].x);
        float2 b1 = __bfloat1622float2(*(const __nv_bfloat162*)&vb[u].y);
        float d = a0.x * b0.x + a0.y * b0.y + a1.x * b1.x + a1.y * b1.y;
        d = warp_sum(d);
        if (lane == u) {
            float cosv = d / (g_znorm[ed[u].x] * g_znorm[ed[u].y]);
            int ci = g_clar[ed[u].x], cj = g_clar[ed[u].y];
            if (!neg) contrib = (ci != cj) ? fmaxf(cosv, 0.0f) : 0.0f;
            else      contrib = (ci == cj) ? -fminf(cosv, 0.0f) : 0.0f;
        }
    }
    block_accum(contrib, 1 + neg);
}

__global__ void finalize_kernel(float* __restrict__ out) {
    double reg = 0.0, s1 = 0.0, s2 = 0.0;
    for (int k = 0; k < 64; k++) {
        reg += g_accs[k];
        s1  += g_accs[64 + k];
        s2  += g_accs[128 + k];
    }
    reg /= (double)NN; s1 /= (double)EE; s2 /= (double)EE;
    out[0] = (float)(LAMB * reg + (1.0 - LAMB) * (s1 + s2));
}

// ---------------- launcher ----------------
extern "C" void kernel_launch(void* const* d_in, const int* in_sizes, int n_in,
                              void* d_out, int out_size) {
    const float *X = 0, *pbW = 0, *nbW = 0, *pdW = 0, *ndW = 0, *regW = 0, *regB = 0;
    const void *pe_raw = 0, *ne_raw = 0, *comm_raw = 0;
    const float* biases[4] = {0, 0, 0, 0};
    int nB = 0, nW2 = 0, nW3 = 0, nEdge = 0, nBig = 0;
    for (int i = 0; i < n_in; i++) {
        int sz = in_sizes[i];
        const void* p = d_in[i];
        if (sz == NN * DD)          { if (nBig == 0) X = (const float*)p; nBig++; }
        else if (sz == 2 * DD * DD) { if (nW2 == 0) pbW = (const float*)p; else nbW = (const float*)p; nW2++; }
        else if (sz == 3 * DD * DD) { if (nW3 == 0) pdW = (const float*)p; else ndW = (const float*)p; nW3++; }
        else if (sz == DD)          { if (nB < 4) biases[nB] = (const float*)p; nB++; }
        else if (sz == 2 * DD * 3)  { regW = (const float*)p; }
        else if (sz == 3)           { regB = (const float*)p; }
        else if (sz == 2 * EE)      { if (nEdge == 0) pe_raw = p; else ne_raw = p; nEdge++; }
        else if (sz == NN)          { comm_raw = p; }
    }
    const float* pbB = biases[0];
    const float* nbB = biases[1];
    const float* pdB = biases[2];
    const float* ndB = biases[3];

    float* out = (float*)d_out;
    float* z_mirror = (out_size >= 1 + NN * 128) ? out + 1 : nullptr;
    float* clar_out = (out_size >= 1 + NN * 128 + NN) ? out + 1 + (size_t)NN * 128 : nullptr;

    float* aggP; cudaGetSymbolAddress((void**)&aggP, g_aggP);
    float* aggN; cudaGetSymbolAddress((void**)&aggN, g_aggN);
    float* agg1; cudaGetSymbolAddress((void**)&agg1, g_agg1);
    float* agg2; cudaGetSymbolAddress((void**)&agg2, g_agg2);
    float* agg3; cudaGetSymbolAddress((void**)&agg3, g_agg3);
    float* agg4; cudaGetSymbolAddress((void**)&agg4, g_agg4);
    int* cntP; cudaGetSymbolAddress((void**)&cntP, g_icntP);
    int* cntN; cudaGetSymbolAddress((void**)&cntN, g_icntN);
    float* hpos; cudaGetSymbolAddress((void**)&hpos, g_hpos);
    float* hneg; cudaGetSymbolAddress((void**)&hneg, g_hneg);
    float* zbuf; cudaGetSymbolAddress((void**)&zbuf, g_z);
    __nv_bfloat16* zh; cudaGetSymbolAddress((void**)&zh, g_zh);

    const int TB = 256;

    detect_kernel<<<1, 32>>>(pe_raw, comm_raw);
    zero_kernel<<<(NN * DD / 4 + TB - 1) / TB, TB>>>();
    convert_kernel<<<(EE + TB - 1) / TB, TB>>>(pe_raw, ne_raw, comm_raw);

    long long sthreads = (long long)(EE / 2) * 16;
    int sblocks = (int)((sthreads + TB - 1) / TB);
    scatter0_both<<<sblocks, TB>>>(X);

    const int DG = 592;   // 4 persistent blocks per SM
    dense_norm_tanh<128><<<DG, TB, 128 * 64 * 4>>>(
        aggP, cntP, X, nullptr, nullptr, pbW, pbB, hpos, 64, 0, nullptr, nullptr);
    dense_norm_tanh<128><<<DG, TB, 128 * 64 * 4>>>(
        aggN, cntN, X, nullptr, nullptr, nbW, nbB, hneg, 64, 0, nullptr, nullptr);

    scatter1_both<<<sblocks, TB>>>();

    dense_norm_tanh<192><<<DG, TB, 192 * 64 * 4>>>(
        agg1, cntP, agg2, cntN, hpos, pdW, pdB, zbuf, 128, 0, z_mirror, zh);
    dense_norm_tanh<192><<<DG, TB, 192 * 64 * 4>>>(
        agg3, cntP, agg4, cntN, hneg, ndW, ndB, zbuf, 128, 64, z_mirror, zh);

    reg_clarify_kernel<<<(NN + TB - 1) / TB, TB>>>(regW, regB, clar_out);

    sim_both<<<2 * SIM_BLOCKS, TB>>>();

    if (out_size >= 1) finalize_kernel<<<1, 1>>>(out);
}

// round 7
// speedup vs baseline: 1.3925x; 1.1540x over previous
#include <cuda_runtime.h>
#include <cuda_bf16.h>
#include <math.h>

#define NN 50000
#define DD 64
#define EE 800000
#define LAMB 0.8f
#define NT 196            // ceil(NN/256)

// ---------------- device workspace ----------------
__device__ __align__(16) float g_hpos[NN * DD];
__device__ __align__(16) float g_hneg[NN * DD];
__device__ __align__(16) float g_z[NN * 128];
__device__ __align__(16) __nv_bfloat16 g_zh[NN * 128];
__device__ __align__(16) float g_znorm[NN];
__device__ int  g_icntP[NN], g_icntN[NN];
__device__ int  g_offP[NN + 1], g_offN[NN + 1];
__device__ int  g_curP[NN], g_curN[NN];
__device__ int  g_colP[EE], g_colN[EE];
__device__ int  g_tsumP[NT], g_tsumN[NT], g_tbaseP[NT], g_tbaseN[NT];
__device__ int  g_clar[NN], g_comm[NN];
__device__ __align__(8) int2 g_peRC[EE], g_neRC[EE];
__device__ int  g_e64, g_c64;
__device__ double g_accs[3 * 64];

// ---------------- helpers ----------------
__device__ __forceinline__ float warp_sum(float v) {
    #pragma unroll
    for (int o = 16; o > 0; o >>= 1) v += __shfl_xor_sync(0xffffffffu, v, o);
    return v;
}

__device__ __forceinline__ void block_accum(float v, int cat) {
    __shared__ float red[8];
    float ws = warp_sum(v);
    int lane = threadIdx.x & 31, w = threadIdx.x >> 5;
    if (lane == 0) red[w] = ws;
    __syncthreads();
    if (w == 0) {
        float s = (lane < (blockDim.x >> 5)) ? red[lane] : 0.0f;
        s = warp_sum(s);
        if (lane == 0) atomicAdd(&g_accs[cat * 64 + (blockIdx.x & 63)], (double)s);
    }
}

// (lane holds agg[2*lane], agg[2*lane+1]) -> (lo = agg[lane], hi = agg[32+lane])
__device__ __forceinline__ void warp_transpose64(float2 s, int lane, float& lo, float& hi) {
    float x0 = __shfl_sync(0xffffffffu, s.x, lane >> 1);
    float y0 = __shfl_sync(0xffffffffu, s.y, lane >> 1);
    lo = (lane & 1) ? y0 : x0;
    float x1 = __shfl_sync(0xffffffffu, s.x, 16 + (lane >> 1));
    float y1 = __shfl_sync(0xffffffffu, s.y, 16 + (lane >> 1));
    hi = (lane & 1) ? y1 : x1;
}

// mean over a node's CSR edge list; lane handles feature pair (2*lane, 2*lane+1)
__device__ __forceinline__ float2 gather_mean(const float* __restrict__ src,
                                              const int* __restrict__ col,
                                              int beg, int end, int lane) {
    float2 s = make_float2(0.f, 0.f);
    const float2* S2 = (const float2*)src;
    int k = beg;
    for (; k + 4 <= end; k += 4) {
        int c0 = col[k], c1 = col[k + 1], c2 = col[k + 2], c3 = col[k + 3];
        float2 v0 = S2[c0 * 32 + lane];
        float2 v1 = S2[c1 * 32 + lane];
        float2 v2 = S2[c2 * 32 + lane];
        float2 v3 = S2[c3 * 32 + lane];
        s.x += v0.x + v1.x + v2.x + v3.x;
        s.y += v0.y + v1.y + v2.y + v3.y;
    }
    for (; k < end; k++) {
        float2 v = S2[col[k] * 32 + lane];
        s.x += v.x; s.y += v.y;
    }
    float inv = 1.0f / fmaxf((float)(end - beg), 1.0f);
    s.x *= inv; s.y *= inv;
    return s;
}

// ---------------- detection / conversion ----------------
__global__ void detect_kernel(const void* pe, const void* cm) {
    if (threadIdx.x == 0 && blockIdx.x == 0) {
        const long long* p = (const long long*)pe;
        int ok = 1;
        for (int k = 0; k < 64; k++) {
            long long v = p[k];
            if (v < 0 || v >= NN) { ok = 0; break; }
        }
        g_e64 = ok;
        const long long* c = (const long long*)cm;
        int ok2 = 1;
        for (int k = 0; k < 64; k++) {
            long long v = c[k];
            if (v < 0 || v >= 3) { ok2 = 0; break; }
        }
        g_c64 = ok2;
    }
}

__global__ void zero_kernel() {
    int i = blockIdx.x * blockDim.x + threadIdx.x;
    if (i < NN) { g_icntP[i] = 0; g_icntN[i] = 0; }
    if (i < 3 * 64) g_accs[i] = 0.0;
}

__device__ __forceinline__ int ld_idx(const void* p, int i, int is64, int lim) {
    long long v = is64 ? ((const long long*)p)[i] : (long long)((const int*)p)[i];
    int x = (int)v;
    return x < 0 ? 0 : (x >= lim ? lim - 1 : x);
}

__global__ void convert_kernel(const void* pe, const void* ne, const void* cm) {
    int i = blockIdx.x * blockDim.x + threadIdx.x;
    int e64 = g_e64, c64 = g_c64;
    if (i < EE) {
        int rp = ld_idx(pe, i, e64, NN);
        int cp = ld_idx(pe, EE + i, e64, NN);
        int rn = ld_idx(ne, i, e64, NN);
        int cn = ld_idx(ne, EE + i, e64, NN);
        g_peRC[i] = make_int2(rp, cp);
        g_neRC[i] = make_int2(rn, cn);
        atomicAdd(&g_icntP[rp], 1);
        atomicAdd(&g_icntN[rn], 1);
    }
    if (i < NN) g_comm[i] = ld_idx(cm, i, c64, 3);
}

// ---------------- CSR build ----------------
__global__ void tile_sum_kernel() {
    __shared__ int shP[256], shN[256];
    int node = blockIdx.x * 256 + threadIdx.x;
    shP[threadIdx.x] = (node < NN) ? g_icntP[node] : 0;
    shN[threadIdx.x] = (node < NN) ? g_icntN[node] : 0;
    __syncthreads();
    for (int s = 128; s > 0; s >>= 1) {
        if (threadIdx.x < s) {
            shP[threadIdx.x] += shP[threadIdx.x + s];
            shN[threadIdx.x] += shN[threadIdx.x + s];
        }
        __syncthreads();
    }
    if (threadIdx.x == 0) { g_tsumP[blockIdx.x] = shP[0]; g_tsumN[blockIdx.x] = shN[0]; }
}

__global__ void tile_scan_kernel() {
    __shared__ int sp[NT], sn[NT];
    if (threadIdx.x < NT) { sp[threadIdx.x] = g_tsumP[threadIdx.x]; sn[threadIdx.x] = g_tsumN[threadIdx.x]; }
    __syncthreads();
    if (threadIdx.x == 0) {
        int a = 0, b = 0;
        for (int t = 0; t < NT; t++) {
            int x = sp[t]; sp[t] = a; a += x;
            int y = sn[t]; sn[t] = b; b += y;
        }
        g_offP[NN] = a; g_offN[NN] = b;
    }
    __syncthreads();
    if (threadIdx.x < NT) { g_tbaseP[threadIdx.x] = sp[threadIdx.x]; g_tbaseN[threadIdx.x] = sn[threadIdx.x]; }
}

__global__ void node_offsets_kernel() {
    __shared__ int bufP[2][256], bufN[2][256];
    int tid = threadIdx.x;
    int node = blockIdx.x * 256 + tid;
    int cp = (node < NN) ? g_icntP[node] : 0;
    int cn = (node < NN) ? g_icntN[node] : 0;
    int cur = 0;
    bufP[0][tid] = cp; bufN[0][tid] = cn;
    __syncthreads();
    for (int off = 1; off < 256; off <<= 1) {
        int vp = bufP[cur][tid] + ((tid >= off) ? bufP[cur][tid - off] : 0);
        int vn = bufN[cur][tid] + ((tid >= off) ? bufN[cur][tid - off] : 0);
        bufP[cur ^ 1][tid] = vp; bufN[cur ^ 1][tid] = vn;
        cur ^= 1;
        __syncthreads();
    }
    if (node < NN) {
        int oP = g_tbaseP[blockIdx.x] + bufP[cur][tid] - cp;
        int oN = g_tbaseN[blockIdx.x] + bufN[cur][tid] - cn;
        g_offP[node] = oP; g_curP[node] = oP;
        g_offN[node] = oN; g_curN[node] = oN;
    }
}

__global__ void fill_kernel() {
    int e = blockIdx.x * blockDim.x + threadIdx.x;
    if (e < EE) {
        int2 p = g_peRC[e];
        g_colP[atomicAdd(&g_curP[p.x], 1)] = p.y;
        int2 n = g_neRC[e];
        g_colN[atomicAdd(&g_curN[n.x], 1)] = n.y;
    }
}

// ---------------- fused layer 0: gather-mean + dense(128->64) + L2norm + tanh ----------------
__global__ void layer0_kernel(const float* __restrict__ X,
                              const float* __restrict__ W, const float* __restrict__ b,
                              const int* __restrict__ off, const int* __restrict__ col,
                              float* __restrict__ out) {
    extern __shared__ float Wsh[];  // 128*64
    for (int t = threadIdx.x; t < 128 * 64; t += blockDim.x) Wsh[t] = W[t];
    __syncthreads();
    int lane = threadIdx.x & 31, wid = threadIdx.x >> 5, wpb = blockDim.x >> 5;
    float2 bias = ((const float2*)b)[lane];
    const float2* W2 = (const float2*)Wsh;

    for (int node = blockIdx.x * wpb + wid; node < NN; node += gridDim.x * wpb) {
        float2 s = gather_mean(X, col, off[node], off[node + 1], lane);
        float r[4];
        warp_transpose64(s, lane, r[0], r[1]);
        r[2] = X[node * 64 + lane];
        r[3] = X[node * 64 + 32 + lane];

        float2 acc = bias;
        #pragma unroll
        for (int k = 0; k < 128; k++) {
            float xk = __shfl_sync(0xffffffffu, r[k >> 5], k & 31);
            float2 w2 = W2[k * 32 + lane];
            acc.x = fmaf(xk, w2.x, acc.x);
            acc.y = fmaf(xk, w2.y, acc.y);
        }
        float sumsq = warp_sum(acc.x * acc.x + acc.y * acc.y);
        float inv = 1.0f / fmaxf(sqrtf(sumsq), 1e-12f);
        float2 ov;
        ov.x = tanhf(acc.x * inv);
        ov.y = tanhf(acc.y * inv);
        ((float2*)(out + (size_t)node * 64))[lane] = ov;
    }
}

// ---------------- fused layer 1: 2 gather-means + dense(192->64) + L2norm + tanh ----------------
__global__ void layer1_kernel(const float* __restrict__ srcA, const float* __restrict__ srcB,
                              const float* __restrict__ self,
                              const float* __restrict__ W, const float* __restrict__ b,
                              const int* __restrict__ offA, const int* __restrict__ colA,
                              const int* __restrict__ offB, const int* __restrict__ colB,
                              int zoff, float* __restrict__ mirror,
                              __nv_bfloat16* __restrict__ zh, float* __restrict__ zbuf) {
    extern __shared__ float Wsh[];  // 192*64
    for (int t = threadIdx.x; t < 192 * 64; t += blockDim.x) Wsh[t] = W[t];
    __syncthreads();
    int lane = threadIdx.x & 31, wid = threadIdx.x >> 5, wpb = blockDim.x >> 5;
    float2 bias = ((const float2*)b)[lane];
    const float2* W2 = (const float2*)Wsh;

    for (int node = blockIdx.x * wpb + wid; node < NN; node += gridDim.x * wpb) {
        float2 sA = gather_mean(srcA, colA, offA[node], offA[node + 1], lane);
        float2 sB = gather_mean(srcB, colB, offB[node], offB[node + 1], lane);
        float r[6];
        warp_transpose64(sA, lane, r[0], r[1]);
        warp_transpose64(sB, lane, r[2], r[3]);
        r[4] = self[node * 64 + lane];
        r[5] = self[node * 64 + 32 + lane];

        float2 acc = bias;
        #pragma unroll
        for (int k = 0; k < 192; k++) {
            float xk = __shfl_sync(0xffffffffu, r[k >> 5], k & 31);
            float2 w2 = W2[k * 32 + lane];
            acc.x = fmaf(xk, w2.x, acc.x);
            acc.y = fmaf(xk, w2.y, acc.y);
        }
        float sumsq = warp_sum(acc.x * acc.x + acc.y * acc.y);
        float inv = 1.0f / fmaxf(sqrtf(sumsq), 1e-12f);
        float2 ov;
        ov.x = tanhf(acc.x * inv);
        ov.y = tanhf(acc.y * inv);
        size_t base = (size_t)node * 128 + zoff + 2 * lane;
        *(float2*)(zbuf + base) = ov;
        if (mirror) {
            // mirror = d_out + 1 is only 4-byte aligned: scalar stores ONLY.
            mirror[base]     = ov.x;
            mirror[base + 1] = ov.y;
        }
        *(__nv_bfloat162*)(zh + base) = __float22bfloat162_rn(ov);
    }
}

// ---------------- logits / argmax / nll / znorm (exact f32 path) ----------------
__global__ void reg_clarify_kernel(const float* __restrict__ Wr, const float* __restrict__ br,
                                   float* __restrict__ out_clar) {
    __shared__ float Ws[384];
    for (int t = threadIdx.x; t < 384; t += blockDim.x) Ws[t] = Wr[t];
    __syncthreads();

    int i = blockIdx.x * blockDim.x + threadIdx.x;
    float term = 0.0f;
    if (i < NN) {
        float l0 = br[0], l1 = br[1], l2 = br[2], sq = 0.0f;
        const float4* zr = (const float4*)(g_z + (size_t)i * 128);
        #pragma unroll
        for (int q = 0; q < 32; q++) {
            float4 v = zr[q];
            int k = q * 4;
            l0 += v.x * Ws[(k+0)*3+0] + v.y * Ws[(k+1)*3+0] + v.z * Ws[(k+2)*3+0] + v.w * Ws[(k+3)*3+0];
            l1 += v.x * Ws[(k+0)*3+1] + v.y * Ws[(k+1)*3+1] + v.z * Ws[(k+2)*3+1] + v.w * Ws[(k+3)*3+1];
            l2 += v.x * Ws[(k+0)*3+2] + v.y * Ws[(k+1)*3+2] + v.z * Ws[(k+2)*3+2] + v.w * Ws[(k+3)*3+2];
            sq += v.x*v.x + v.y*v.y + v.z*v.z + v.w*v.w;
        }
        g_znorm[i] = fmaxf(sqrtf(sq), 1e-8f);

        float m = fmaxf(l0, fmaxf(l1, l2));
        float lse = m + logf(expf(l0 - m) + expf(l1 - m) + expf(l2 - m));
        int cm = g_comm[i];
        float lc = (cm == 0) ? l0 : ((cm == 1) ? l1 : l2);
        term = lse - lc;

        int cls = 0; float best = l0;
        if (l1 > best) { best = l1; cls = 1; }
        if (l2 > best) { best = l2; cls = 2; }
        g_clar[i] = cls;
        if (out_clar) out_clar[i] = (float)cls;
    }
    block_accum(term, 0);
}

// ---------------- cosine sim losses: bf16 rows, 4 edges per warp ----------------
#define SIM_EPW 4
#define SIM_BLOCKS (EE / (SIM_EPW * 8))
__global__ void sim_both() {
    int neg = (blockIdx.x >= SIM_BLOCKS) ? 1 : 0;
    int bid = neg ? blockIdx.x - SIM_BLOCKS : blockIdx.x;
    int warp = bid * 8 + (threadIdx.x >> 5);
    int lane = threadIdx.x & 31;
    int base = warp * SIM_EPW;
    const int2* RC = neg ? g_neRC : g_peRC;

    int2 ed[SIM_EPW];
    #pragma unroll
    for (int u = 0; u < SIM_EPW; u++) ed[u] = RC[base + u];

    uint2 va[SIM_EPW], vb[SIM_EPW];
    #pragma unroll
    for (int u = 0; u < SIM_EPW; u++) {
        va[u] = ((const uint2*)(g_zh + (size_t)ed[u].x * 128))[lane];
        vb[u] = ((const uint2*)(g_zh + (size_t)ed[u].y * 128))[lane];
    }

    float contrib = 0.0f;
    #pragma unroll
    for (int u = 0; u < SIM_EPW; u++) {
        float2 a0 = __bfloat1622float2(*(const __nv_bfloat162*)&va[u].x);
        float2 a1 = __bfloat1622float2(*(const __nv_bfloat162*)&va[u].y);
        float2 b0 = __bfloat1622float2(*(const __nv_bfloat162*)&vb[u].x);
        float2 b1 = __bfloat1622float2(*(const __nv_bfloat162*)&vb[u].y);
        float d = a0.x * b0.x + a0.y * b0.y + a1.x * b1.x + a1.y * b1.y;
        d = warp_sum(d);
        if (lane == u) {
            float cosv = d / (g_znorm[ed[u].x] * g_znorm[ed[u].y]);
            int ci = g_clar[ed[u].x], cj = g_clar[ed[u].y];
            if (!neg) contrib = (ci != cj) ? fmaxf(cosv, 0.0f) : 0.0f;
            else      contrib = (ci == cj) ? -fminf(cosv, 0.0f) : 0.0f;
        }
    }
    block_accum(contrib, 1 + neg);
}

__global__ void finalize_kernel(float* __restrict__ out) {
    double reg = 0.0, s1 = 0.0, s2 = 0.0;
    for (int k = 0; k < 64; k++) {
        reg += g_accs[k];
        s1  += g_accs[64 + k];
        s2  += g_accs[128 + k];
    }
    reg /= (double)NN; s1 /= (double)EE; s2 /= (double)EE;
    out[0] = (float)(LAMB * reg + (1.0 - LAMB) * (s1 + s2));
}

// ---------------- launcher ----------------
extern "C" void kernel_launch(void* const* d_in, const int* in_sizes, int n_in,
                              void* d_out, int out_size) {
    const float *X = 0, *pbW = 0, *nbW = 0, *pdW = 0, *ndW = 0, *regW = 0, *regB = 0;
    const void *pe_raw = 0, *ne_raw = 0, *comm_raw = 0;
    const float* biases[4] = {0, 0, 0, 0};
    int nB = 0, nW2 = 0, nW3 = 0, nEdge = 0, nBig = 0;
    for (int i = 0; i < n_in; i++) {
        int sz = in_sizes[i];
        const void* p = d_in[i];
        if (sz == NN * DD)          { if (nBig == 0) X = (const float*)p; nBig++; }
        else if (sz == 2 * DD * DD) { if (nW2 == 0) pbW = (const float*)p; else nbW = (const float*)p; nW2++; }
        else if (sz == 3 * DD * DD) { if (nW3 == 0) pdW = (const float*)p; else ndW = (const float*)p; nW3++; }
        else if (sz == DD)          { if (nB < 4) biases[nB] = (const float*)p; nB++; }
        else if (sz == 2 * DD * 3)  { regW = (const float*)p; }
        else if (sz == 3)           { regB = (const float*)p; }
        else if (sz == 2 * EE)      { if (nEdge == 0) pe_raw = p; else ne_raw = p; nEdge++; }
        else if (sz == NN)          { comm_raw = p; }
    }
    const float* pbB = biases[0];
    const float* nbB = biases[1];
    const float* pdB = biases[2];
    const float* ndB = biases[3];

    float* out = (float*)d_out;
    float* z_mirror = (out_size >= 1 + NN * 128) ? out + 1 : nullptr;
    float* clar_out = (out_size >= 1 + NN * 128 + NN) ? out + 1 + (size_t)NN * 128 : nullptr;

    float* hpos; cudaGetSymbolAddress((void**)&hpos, g_hpos);
    float* hneg; cudaGetSymbolAddress((void**)&hneg, g_hneg);
    float* zbuf; cudaGetSymbolAddress((void**)&zbuf, g_z);
    __nv_bfloat16* zh; cudaGetSymbolAddress((void**)&zh, g_zh);
    int* offP; cudaGetSymbolAddress((void**)&offP, g_offP);
    int* offN; cudaGetSymbolAddress((void**)&offN, g_offN);
    int* colP; cudaGetSymbolAddress((void**)&colP, g_colP);
    int* colN; cudaGetSymbolAddress((void**)&colN, g_colN);

    const int TB = 256;

    detect_kernel<<<1, 32>>>(pe_raw, comm_raw);
    zero_kernel<<<(NN + TB - 1) / TB, TB>>>();
    convert_kernel<<<(EE + TB - 1) / TB, TB>>>(pe_raw, ne_raw, comm_raw);

    // CSR build
    tile_sum_kernel<<<NT, 256>>>();
    tile_scan_kernel<<<1, 256>>>();
    node_offsets_kernel<<<NT, 256>>>();
    fill_kernel<<<(EE + TB - 1) / TB, TB>>>();

    const int DG = 592;  // persistent grid
    // layer 0
    layer0_kernel<<<DG, TB, 128 * 64 * 4>>>(X, pbW, pbB, offP, colP, hpos);
    layer0_kernel<<<DG, TB, 128 * 64 * 4>>>(X, nbW, nbB, offN, colN, hneg);
    // layer 1 (balance-theory cross wiring)
    layer1_kernel<<<DG, TB, 192 * 64 * 4>>>(hpos, hneg, hpos, pdW, pdB,
                                            offP, colP, offN, colN, 0, z_mirror, zh, zbuf);
    layer1_kernel<<<DG, TB, 192 * 64 * 4>>>(hneg, hpos, hneg, ndW, ndB,
                                            offP, colP, offN, colN, 64, z_mirror, zh, zbuf);

    reg_clarify_kernel<<<(NN + TB - 1) / TB, TB>>>(regW, regB, clar_out);
    sim_both<<<2 * SIM_BLOCKS, TB>>>();
    if (out_size >= 1) finalize_kernel<<<1, 1>>>(out);
}

// round 8
// speedup vs baseline: 1.6177x; 1.1617x over previous
#include <cuda_runtime.h>
#include <cuda_bf16.h>
#include <math.h>

#define NN 50000
#define DD 64
#define EE 800000
#define LAMB 0.8f
#define NT 196            // ceil(NN/256)

// ---------------- device workspace ----------------
__device__ __align__(16) float g_hpos[NN * DD];
__device__ __align__(16) float g_hneg[NN * DD];
__device__ __align__(16) float g_z[NN * 128];
__device__ __align__(16) __nv_bfloat16 g_zh[NN * 128];   // normalized rows
__device__ int  g_icntP[NN], g_icntN[NN];
__device__ int  g_offP[NN + 1], g_offN[NN + 1];
__device__ int  g_curP[NN], g_curN[NN];
__device__ int  g_colP[EE], g_colN[EE];
__device__ int  g_tsumP[NT], g_tsumN[NT], g_tbaseP[NT], g_tbaseN[NT];
__device__ int  g_clar[NN], g_comm[NN];
__device__ __align__(8) int2 g_peRC[EE], g_neRC[EE];
__device__ int  g_e64, g_c64;
__device__ double g_accs[3 * 64];

// ---------------- helpers ----------------
__device__ __forceinline__ float warp_sum(float v) {
    #pragma unroll
    for (int o = 16; o > 0; o >>= 1) v += __shfl_xor_sync(0xffffffffu, v, o);
    return v;
}

__device__ __forceinline__ void block_accum(float v, int cat) {
    __shared__ float red[8];
    float ws = warp_sum(v);
    int lane = threadIdx.x & 31, w = threadIdx.x >> 5;
    if (lane == 0) red[w] = ws;
    __syncthreads();
    if (w == 0) {
        float s = (lane < (blockDim.x >> 5)) ? red[lane] : 0.0f;
        s = warp_sum(s);
        if (lane == 0) atomicAdd(&g_accs[cat * 64 + (blockIdx.x & 63)], (double)s);
    }
}

__device__ __forceinline__ void warp_transpose64(float2 s, int lane, float& lo, float& hi) {
    float x0 = __shfl_sync(0xffffffffu, s.x, lane >> 1);
    float y0 = __shfl_sync(0xffffffffu, s.y, lane >> 1);
    lo = (lane & 1) ? y0 : x0;
    float x1 = __shfl_sync(0xffffffffu, s.x, 16 + (lane >> 1));
    float y1 = __shfl_sync(0xffffffffu, s.y, 16 + (lane >> 1));
    hi = (lane & 1) ? y1 : x1;
}

// mean over a node's CSR list (exact R7 arithmetic shape)
__device__ __forceinline__ float2 gather_mean(const float* __restrict__ src,
                                              const int* __restrict__ col,
                                              int beg, int end, int lane) {
    float2 s = make_float2(0.f, 0.f);
    const float2* S2 = (const float2*)src;
    int k = beg;
    for (; k + 4 <= end; k += 4) {
        int c0 = col[k], c1 = col[k + 1], c2 = col[k + 2], c3 = col[k + 3];
        float2 v0 = S2[c0 * 32 + lane];
        float2 v1 = S2[c1 * 32 + lane];
        float2 v2 = S2[c2 * 32 + lane];
        float2 v3 = S2[c3 * 32 + lane];
        s.x += v0.x + v1.x + v2.x + v3.x;
        s.y += v0.y + v1.y + v2.y + v3.y;
    }
    for (; k < end; k++) {
        float2 v = S2[col[k] * 32 + lane];
        s.x += v.x; s.y += v.y;
    }
    float inv = 1.0f / fmaxf((float)(end - beg), 1.0f);
    s.x *= inv; s.y *= inv;
    return s;
}

// same but gathers two arrays along one col list (per-array sums keep R7 grouping)
__device__ __forceinline__ void gather_mean2(const float* __restrict__ A,
                                             const float* __restrict__ B,
                                             const int* __restrict__ col,
                                             int beg, int end, int lane,
                                             float2& ra, float2& rb) {
    float2 sa = make_float2(0.f, 0.f), sb = make_float2(0.f, 0.f);
    const float2* A2 = (const float2*)A;
    const float2* B2 = (const float2*)B;
    int k = beg;
    for (; k + 4 <= end; k += 4) {
        int c0 = col[k], c1 = col[k + 1], c2 = col[k + 2], c3 = col[k + 3];
        float2 a0 = A2[c0 * 32 + lane], a1 = A2[c1 * 32 + lane];
        float2 a2 = A2[c2 * 32 + lane], a3 = A2[c3 * 32 + lane];
        float2 b0 = B2[c0 * 32 + lane], b1 = B2[c1 * 32 + lane];
        float2 b2 = B2[c2 * 32 + lane], b3 = B2[c3 * 32 + lane];
        sa.x += a0.x + a1.x + a2.x + a3.x;
        sa.y += a0.y + a1.y + a2.y + a3.y;
        sb.x += b0.x + b1.x + b2.x + b3.x;
        sb.y += b0.y + b1.y + b2.y + b3.y;
    }
    for (; k < end; k++) {
        int c = col[k];
        float2 a = A2[c * 32 + lane];
        float2 b = B2[c * 32 + lane];
        sa.x += a.x; sa.y += a.y;
        sb.x += b.x; sb.y += b.y;
    }
    float inv = 1.0f / fmaxf((float)(end - beg), 1.0f);
    ra.x = sa.x * inv; ra.y = sa.y * inv;
    rb.x = sb.x * inv; rb.y = sb.y * inv;
}

// ---------------- detection / conversion ----------------
__global__ void detect_kernel(const void* pe, const void* cm) {
    if (threadIdx.x == 0 && blockIdx.x == 0) {
        const long long* p = (const long long*)pe;
        int ok = 1;
        for (int k = 0; k < 64; k++) {
            long long v = p[k];
            if (v < 0 || v >= NN) { ok = 0; break; }
        }
        g_e64 = ok;
        const long long* c = (const long long*)cm;
        int ok2 = 1;
        for (int k = 0; k < 64; k++) {
            long long v = c[k];
            if (v < 0 || v >= 3) { ok2 = 0; break; }
        }
        g_c64 = ok2;
    }
}

__global__ void zero_kernel() {
    int i = blockIdx.x * blockDim.x + threadIdx.x;
    if (i < NN) { g_icntP[i] = 0; g_icntN[i] = 0; }
    if (i < 3 * 64) g_accs[i] = 0.0;
}

__device__ __forceinline__ int ld_idx(const void* p, int i, int is64, int lim) {
    long long v = is64 ? ((const long long*)p)[i] : (long long)((const int*)p)[i];
    int x = (int)v;
    return x < 0 ? 0 : (x >= lim ? lim - 1 : x);
}

__global__ void convert_kernel(const void* pe, const void* ne, const void* cm) {
    int i = blockIdx.x * blockDim.x + threadIdx.x;
    int e64 = g_e64, c64 = g_c64;
    if (i < EE) {
        int rp = ld_idx(pe, i, e64, NN);
        int cp = ld_idx(pe, EE + i, e64, NN);
        int rn = ld_idx(ne, i, e64, NN);
        int cn = ld_idx(ne, EE + i, e64, NN);
        g_peRC[i] = make_int2(rp, cp);
        g_neRC[i] = make_int2(rn, cn);
        atomicAdd(&g_icntP[rp], 1);
        atomicAdd(&g_icntN[rn], 1);
    }
    if (i < NN) g_comm[i] = ld_idx(cm, i, c64, 3);
}

// ---------------- CSR build ----------------
__global__ void tile_sum_kernel() {
    __shared__ int shP[256], shN[256];
    int node = blockIdx.x * 256 + threadIdx.x;
    shP[threadIdx.x] = (node < NN) ? g_icntP[node] : 0;
    shN[threadIdx.x] = (node < NN) ? g_icntN[node] : 0;
    __syncthreads();
    for (int s = 128; s > 0; s >>= 1) {
        if (threadIdx.x < s) {
            shP[threadIdx.x] += shP[threadIdx.x + s];
            shN[threadIdx.x] += shN[threadIdx.x + s];
        }
        __syncthreads();
    }
    if (threadIdx.x == 0) { g_tsumP[blockIdx.x] = shP[0]; g_tsumN[blockIdx.x] = shN[0]; }
}

__global__ void tile_scan_kernel() {
    __shared__ int sp[NT], sn[NT];
    if (threadIdx.x < NT) { sp[threadIdx.x] = g_tsumP[threadIdx.x]; sn[threadIdx.x] = g_tsumN[threadIdx.x]; }
    __syncthreads();
    if (threadIdx.x == 0) {
        int a = 0, b = 0;
        for (int t = 0; t < NT; t++) {
            int x = sp[t]; sp[t] = a; a += x;
            int y = sn[t]; sn[t] = b; b += y;
        }
        g_offP[NN] = a; g_offN[NN] = b;
    }
    __syncthreads();
    if (threadIdx.x < NT) { g_tbaseP[threadIdx.x] = sp[threadIdx.x]; g_tbaseN[threadIdx.x] = sn[threadIdx.x]; }
}

__global__ void node_offsets_kernel() {
    __shared__ int bufP[2][256], bufN[2][256];
    int tid = threadIdx.x;
    int node = blockIdx.x * 256 + tid;
    int cp = (node < NN) ? g_icntP[node] : 0;
    int cn = (node < NN) ? g_icntN[node] : 0;
    int cur = 0;
    bufP[0][tid] = cp; bufN[0][tid] = cn;
    __syncthreads();
    for (int off = 1; off < 256; off <<= 1) {
        int vp = bufP[cur][tid] + ((tid >= off) ? bufP[cur][tid - off] : 0);
        int vn = bufN[cur][tid] + ((tid >= off) ? bufN[cur][tid - off] : 0);
        bufP[cur ^ 1][tid] = vp; bufN[cur ^ 1][tid] = vn;
        cur ^= 1;
        __syncthreads();
    }
    if (node < NN) {
        int oP = g_tbaseP[blockIdx.x] + bufP[cur][tid] - cp;
        int oN = g_tbaseN[blockIdx.x] + bufN[cur][tid] - cn;
        g_offP[node] = oP; g_curP[node] = oP;
        g_offN[node] = oN; g_curN[node] = oN;
    }
}

__global__ void fill_kernel() {
    int e = blockIdx.x * blockDim.x + threadIdx.x;
    if (e < EE) {
        int2 p = g_peRC[e];
        g_colP[atomicAdd(&g_curP[p.x], 1)] = p.y;
        int2 n = g_neRC[e];
        g_colN[atomicAdd(&g_curN[n.x], 1)] = n.y;
    }
}

// ---------------- fused layer 0 (pos+neg): gather + dense(128->64) + norm + tanh ----------------
__global__ void layer0_fused(const float* __restrict__ X,
                             const float* __restrict__ WP, const float* __restrict__ bP,
                             const float* __restrict__ WN, const float* __restrict__ bN) {
    extern __shared__ float Wsh[];  // [0:8192) WP, [8192:16384) WN
    for (int t = threadIdx.x; t < 128 * 64; t += blockDim.x) {
        Wsh[t] = WP[t];
        Wsh[8192 + t] = WN[t];
    }
    __syncthreads();
    int lane = threadIdx.x & 31, wid = threadIdx.x >> 5, wpb = blockDim.x >> 5;
    float2 biasP = ((const float2*)bP)[lane];
    float2 biasN = ((const float2*)bN)[lane];
    const float2* WP2 = (const float2*)Wsh;
    const float2* WN2 = (const float2*)(Wsh + 8192);

    for (int node = blockIdx.x * wpb + wid; node < NN; node += gridDim.x * wpb) {
        float2 sP = gather_mean(X, g_colP, g_offP[node], g_offP[node + 1], lane);
        float2 sN = gather_mean(X, g_colN, g_offN[node], g_offN[node + 1], lane);
        float rp[4], rn[4];
        warp_transpose64(sP, lane, rp[0], rp[1]);
        warp_transpose64(sN, lane, rn[0], rn[1]);
        rp[2] = X[node * 64 + lane];
        rp[3] = X[node * 64 + 32 + lane];
        rn[2] = rp[2]; rn[3] = rp[3];

        float2 accP = biasP, accN = biasN;
        #pragma unroll
        for (int k = 0; k < 128; k++) {
            float xp = __shfl_sync(0xffffffffu, rp[k >> 5], k & 31);
            float xn = __shfl_sync(0xffffffffu, rn[k >> 5], k & 31);
            float2 wp = WP2[k * 32 + lane];
            float2 wn = WN2[k * 32 + lane];
            accP.x = fmaf(xp, wp.x, accP.x);
            accP.y = fmaf(xp, wp.y, accP.y);
            accN.x = fmaf(xn, wn.x, accN.x);
            accN.y = fmaf(xn, wn.y, accN.y);
        }
        float ssP = warp_sum(accP.x * accP.x + accP.y * accP.y);
        float ssN = warp_sum(accN.x * accN.x + accN.y * accN.y);
        float ivP = 1.0f / fmaxf(sqrtf(ssP), 1e-12f);
        float ivN = 1.0f / fmaxf(sqrtf(ssN), 1e-12f);
        float2 op, on;
        op.x = tanhf(accP.x * ivP); op.y = tanhf(accP.y * ivP);
        on.x = tanhf(accN.x * ivN); on.y = tanhf(accN.y * ivN);
        ((float2*)(g_hpos + (size_t)node * 64))[lane] = op;
        ((float2*)(g_hneg + (size_t)node * 64))[lane] = on;
    }
}

// ---------------- fused layer 1 (pos+neg): 4 gathers + 2x dense(192->64) + norm + tanh ----------------
__global__ void layer1_fused(const float* __restrict__ WP, const float* __restrict__ bP,
                             const float* __restrict__ WN, const float* __restrict__ bN,
                             float* __restrict__ mirror) {
    extern __shared__ float Wsh[];  // [0:12288) WP, [12288:24576) WN
    for (int t = threadIdx.x; t < 192 * 64; t += blockDim.x) {
        Wsh[t] = WP[t];
        Wsh[12288 + t] = WN[t];
    }
    __syncthreads();
    int lane = threadIdx.x & 31, wid = threadIdx.x >> 5, wpb = blockDim.x >> 5;
    float2 biasP = ((const float2*)bP)[lane];
    float2 biasN = ((const float2*)bN)[lane];
    const float2* WP2 = (const float2*)Wsh;
    const float2* WN2 = (const float2*)(Wsh + 12288);

    for (int node = blockIdx.x * wpb + wid; node < NN; node += gridDim.x * wpb) {
        // posmean(hpos)=s1, posmean(hneg)=s3 ; negmean(hneg)=s2, negmean(hpos)=s4
        float2 s1, s3, s2, s4;
        gather_mean2(g_hpos, g_hneg, g_colP, g_offP[node], g_offP[node + 1], lane, s1, s3);
        gather_mean2(g_hneg, g_hpos, g_colN, g_offN[node], g_offN[node + 1], lane, s2, s4);

        float rp[6], rn[6];
        warp_transpose64(s1, lane, rp[0], rp[1]);
        warp_transpose64(s2, lane, rp[2], rp[3]);
        warp_transpose64(s3, lane, rn[0], rn[1]);
        warp_transpose64(s4, lane, rn[2], rn[3]);
        rp[4] = g_hpos[node * 64 + lane];
        rp[5] = g_hpos[node * 64 + 32 + lane];
        rn[4] = g_hneg[node * 64 + lane];
        rn[5] = g_hneg[node * 64 + 32 + lane];

        float2 accP = biasP, accN = biasN;
        #pragma unroll
        for (int k = 0; k < 192; k++) {
            float xp = __shfl_sync(0xffffffffu, rp[k >> 5], k & 31);
            float xn = __shfl_sync(0xffffffffu, rn[k >> 5], k & 31);
            float2 wp = WP2[k * 32 + lane];
            float2 wn = WN2[k * 32 + lane];
            accP.x = fmaf(xp, wp.x, accP.x);
            accP.y = fmaf(xp, wp.y, accP.y);
            accN.x = fmaf(xn, wn.x, accN.x);
            accN.y = fmaf(xn, wn.y, accN.y);
        }
        float ssP = warp_sum(accP.x * accP.x + accP.y * accP.y);
        float ssN = warp_sum(accN.x * accN.x + accN.y * accN.y);
        float ivP = 1.0f / fmaxf(sqrtf(ssP), 1e-12f);
        float ivN = 1.0f / fmaxf(sqrtf(ssN), 1e-12f);
        float2 zp, zn;
        zp.x = tanhf(accP.x * ivP); zp.y = tanhf(accP.y * ivP);
        zn.x = tanhf(accN.x * ivN); zn.y = tanhf(accN.y * ivN);

        size_t bp = (size_t)node * 128 + 2 * lane;
        size_t bn = bp + 64;
        *(float2*)(g_z + bp) = zp;
        *(float2*)(g_z + bn) = zn;
        if (mirror) {   // d_out+1: 4-byte aligned only -> scalar stores
            mirror[bp] = zp.x; mirror[bp + 1] = zp.y;
            mirror[bn] = zn.x; mirror[bn + 1] = zn.y;
        }
        // normalized bf16 shadow for the sim pass
        float ssz = warp_sum(zp.x * zp.x + zp.y * zp.y + zn.x * zn.x + zn.y * zn.y);
        float ivz = 1.0f / fmaxf(sqrtf(ssz), 1e-8f);
        float2 hp, hn;
        hp.x = zp.x * ivz; hp.y = zp.y * ivz;
        hn.x = zn.x * ivz; hn.y = zn.y * ivz;
        *(__nv_bfloat162*)(g_zh + bp) = __float22bfloat162_rn(hp);
        *(__nv_bfloat162*)(g_zh + bn) = __float22bfloat162_rn(hn);
    }
}

// ---------------- logits / argmax / nll (exact f32 path — unchanged numerics) ----------------
__global__ void reg_clarify_kernel(const float* __restrict__ Wr, const float* __restrict__ br,
                                   float* __restrict__ out_clar) {
    __shared__ float Ws[384];
    for (int t = threadIdx.x; t < 384; t += blockDim.x) Ws[t] = Wr[t];
    __syncthreads();

    int i = blockIdx.x * blockDim.x + threadIdx.x;
    float term = 0.0f;
    if (i < NN) {
        float l0 = br[0], l1 = br[1], l2 = br[2];
        const float4* zr = (const float4*)(g_z + (size_t)i * 128);
        #pragma unroll
        for (int q = 0; q < 32; q++) {
            float4 v = zr[q];
            int k = q * 4;
            l0 += v.x * Ws[(k+0)*3+0] + v.y * Ws[(k+1)*3+0] + v.z * Ws[(k+2)*3+0] + v.w * Ws[(k+3)*3+0];
            l1 += v.x * Ws[(k+0)*3+1] + v.y * Ws[(k+1)*3+1] + v.z * Ws[(k+2)*3+1] + v.w * Ws[(k+3)*3+1];
            l2 += v.x * Ws[(k+0)*3+2] + v.y * Ws[(k+1)*3+2] + v.z * Ws[(k+2)*3+2] + v.w * Ws[(k+3)*3+2];
        }
        float m = fmaxf(l0, fmaxf(l1, l2));
        float lse = m + logf(expf(l0 - m) + expf(l1 - m) + expf(l2 - m));
        int cm = g_comm[i];
        float lc = (cm == 0) ? l0 : ((cm == 1) ? l1 : l2);
        term = lse - lc;

        int cls = 0; float best = l0;
        if (l1 > best) { best = l1; cls = 1; }
        if (l2 > best) { best = l2; cls = 2; }
        g_clar[i] = cls;
        if (out_clar) out_clar[i] = (float)cls;
    }
    block_accum(term, 0);
}

// ---------------- cosine sim losses: normalized bf16 rows, 4 edges/warp ----------------
#define SIM_EPW 4
#define SIM_BLOCKS (EE / (SIM_EPW * 8))
__global__ void sim_both() {
    int neg = (blockIdx.x >= SIM_BLOCKS) ? 1 : 0;
    int bid = neg ? blockIdx.x - SIM_BLOCKS : blockIdx.x;
    int warp = bid * 8 + (threadIdx.x >> 5);
    int lane = threadIdx.x & 31;
    int base = warp * SIM_EPW;
    const int2* RC = neg ? g_neRC : g_peRC;

    int2 ed[SIM_EPW];
    #pragma unroll
    for (int u = 0; u < SIM_EPW; u++) ed[u] = RC[base + u];

    uint2 va[SIM_EPW], vb[SIM_EPW];
    #pragma unroll
    for (int u = 0; u < SIM_EPW; u++) {
        va[u] = ((const uint2*)(g_zh + (size_t)ed[u].x * 128))[lane];
        vb[u] = ((const uint2*)(g_zh + (size_t)ed[u].y * 128))[lane];
    }

    float contrib = 0.0f;
    #pragma unroll
    for (int u = 0; u < SIM_EPW; u++) {
        float2 a0 = __bfloat1622float2(*(const __nv_bfloat162*)&va[u].x);
        float2 a1 = __bfloat1622float2(*(const __nv_bfloat162*)&va[u].y);
        float2 b0 = __bfloat1622float2(*(const __nv_bfloat162*)&vb[u].x);
        float2 b1 = __bfloat1622float2(*(const __nv_bfloat162*)&vb[u].y);
        float d = a0.x * b0.x + a0.y * b0.y + a1.x * b1.x + a1.y * b1.y;
        d = warp_sum(d);
        if (lane == u) {
            int ci = g_clar[ed[u].x], cj = g_clar[ed[u].y];
            if (!neg) contrib = (ci != cj) ? fmaxf(d, 0.0f) : 0.0f;
            else      contrib = (ci == cj) ? -fminf(d, 0.0f) : 0.0f;
        }
    }
    block_accum(contrib, 1 + neg);
}

__global__ void finalize_kernel(float* __restrict__ out) {
    double reg = 0.0, s1 = 0.0, s2 = 0.0;
    for (int k = 0; k < 64; k++) {
        reg += g_accs[k];
        s1  += g_accs[64 + k];
        s2  += g_accs[128 + k];
    }
    reg /= (double)NN; s1 /= (double)EE; s2 /= (double)EE;
    out[0] = (float)(LAMB * reg + (1.0 - LAMB) * (s1 + s2));
}

// ---------------- launcher ----------------
extern "C" void kernel_launch(void* const* d_in, const int* in_sizes, int n_in,
                              void* d_out, int out_size) {
    const float *X = 0, *pbW = 0, *nbW = 0, *pdW = 0, *ndW = 0, *regW = 0, *regB = 0;
    const void *pe_raw = 0, *ne_raw = 0, *comm_raw = 0;
    const float* biases[4] = {0, 0, 0, 0};
    int nB = 0, nW2 = 0, nW3 = 0, nEdge = 0, nBig = 0;
    for (int i = 0; i < n_in; i++) {
        int sz = in_sizes[i];
        const void* p = d_in[i];
        if (sz == NN * DD)          { if (nBig == 0) X = (const float*)p; nBig++; }
        else if (sz == 2 * DD * DD) { if (nW2 == 0) pbW = (const float*)p; else nbW = (const float*)p; nW2++; }
        else if (sz == 3 * DD * DD) { if (nW3 == 0) pdW = (const float*)p; else ndW = (const float*)p; nW3++; }
        else if (sz == DD)          { if (nB < 4) biases[nB] = (const float*)p; nB++; }
        else if (sz == 2 * DD * 3)  { regW = (const float*)p; }
        else if (sz == 3)           { regB = (const float*)p; }
        else if (sz == 2 * EE)      { if (nEdge == 0) pe_raw = p; else ne_raw = p; nEdge++; }
        else if (sz == NN)          { comm_raw = p; }
    }
    const float* pbB = biases[0];
    const float* nbB = biases[1];
    const float* pdB = biases[2];
    const float* ndB = biases[3];

    float* out = (float*)d_out;
    float* z_mirror = (out_size >= 1 + NN * 128) ? out + 1 : nullptr;
    float* clar_out = (out_size >= 1 + NN * 128 + NN) ? out + 1 + (size_t)NN * 128 : nullptr;

    const int TB = 256;

    detect_kernel<<<1, 32>>>(pe_raw, comm_raw);
    zero_kernel<<<(NN + TB - 1) / TB, TB>>>();
    convert_kernel<<<(EE + TB - 1) / TB, TB>>>(pe_raw, ne_raw, comm_raw);

    tile_sum_kernel<<<NT, 256>>>();
    tile_scan_kernel<<<1, 256>>>();
    node_offsets_kernel<<<NT, 256>>>();
    fill_kernel<<<(EE + TB - 1) / TB, TB>>>();

    cudaFuncSetAttribute(layer0_fused, cudaFuncAttributeMaxDynamicSharedMemorySize, 65536);
    cudaFuncSetAttribute(layer1_fused, cudaFuncAttributeMaxDynamicSharedMemorySize, 98304);

    layer0_fused<<<444, 384, 65536>>>(X, pbW, pbB, nbW, nbB);
    layer1_fused<<<296, 384, 98304>>>(pdW, pdB, ndW, ndB, z_mirror);

    reg_clarify_kernel<<<(NN + TB - 1) / TB, TB>>>(regW, regB, clar_out);
    sim_both<<<2 * SIM_BLOCKS, TB>>>();
    if (out_size >= 1) finalize_kernel<<<1, 1>>>(out);
}